// round 5
// baseline (speedup 1.0000x reference)
#include <cuda_runtime.h>
#include <cuda_bf16.h>
#include <cstdint>

// TypeConditionalLinear on sm_100 (no tcgen05 on non-'a' target).
// out[n] = input[n] @ weight[i_type[n]].T + bias[i_type[n]]
// N=16384, IN=OUT=512, T=16. fp32 in/out.
//
// Round 5: hoist the fp32->bf16(hi,lo) split OUT of the GEMM mainloop.
//   Phase 1: bucket tokens by type (hist/scan/scatter).
//   Phase 1.5: convert W and permuted-A once into __device__ bf16 hi/lo buffers.
//   Phase 2: gather-GEMM, producers = pure cp.async (4x16B/thread/slab),
//            4-stage pipeline, consumers = ldmatrix + mma.sync m16n8k16 bf16
//            3-product split (hi*hi + lo*hi + hi*lo).

#define N_TOK   16384
#define IN_F    512
#define OUT_F   512
#define N_TYPES 16

#define BM 128
#define BN 128
#define BK 32
#define N_SLABS (IN_F / BK)               // 16
#define MAX_TILES (N_TOK / BM + N_TYPES)  // 144
#define NTHREADS 512
#define N_STAGES 4

#define ROW_B   80                        // smem row stride (32 bf16 = 64B + 16B pad)
#define TILE_B  (128 * ROW_B)             // 10240
#define A_HI    0
#define A_LO    TILE_B
#define B_HI    (2 * TILE_B)
#define B_LO    (3 * TILE_B)
#define STAGE_B (4 * TILE_B)              // 40960
#define SM_TOKEN 0
#define SM_BIAS  512
#define SM_STAGE 1024
#define SMEM_TOTAL (SM_STAGE + N_STAGES * STAGE_B)   // 164864

// ---------------- scratch ----------------
__device__ int g_counts[N_TYPES];
__device__ int g_fill[N_TYPES];
__device__ int g_offsets[N_TYPES + 1];
__device__ int g_perm[N_TOK];
__device__ int g_tile_type[MAX_TILES];
__device__ int g_tile_start[MAX_TILES];
__device__ int g_tile_rows[MAX_TILES];
__device__ int g_num_tiles;
__device__ int g_odd_or;     // !=0 => i_type is int32

// pre-split operand buffers (A permuted into g_perm order; +128 rows padding)
__device__ __nv_bfloat16 g_Ahi[(N_TOK + BM) * IN_F];
__device__ __nv_bfloat16 g_Alo[(N_TOK + BM) * IN_F];
__device__ __nv_bfloat16 g_Whi[N_TYPES * OUT_F * IN_F];
__device__ __nv_bfloat16 g_Wlo[N_TYPES * OUT_F * IN_F];

__device__ __forceinline__ int load_type(const void* it, int n) {
    if (g_odd_or == 0) return ((int)((const long long*)it)[n]) & (N_TYPES - 1);
    return ((const int*)it)[n] & (N_TYPES - 1);
}

// ---------------- phase 1 ----------------
__global__ void tcl_zero_kernel() {
    int t = threadIdx.x;
    if (t < N_TYPES) { g_counts[t] = 0; g_fill[t] = 0; }
    if (t == 0) g_odd_or = 0;
}

__global__ void tcl_detect_kernel(const int* __restrict__ it32) {
    int i = blockIdx.x * blockDim.x + threadIdx.x;
    int v = it32[2 * i + 1];
    #pragma unroll
    for (int s = 16; s > 0; s >>= 1) v |= __shfl_xor_sync(0xffffffffu, v, s);
    if ((threadIdx.x & 31) == 0 && v) atomicOr(&g_odd_or, v);
}

__global__ void tcl_hist_kernel(const void* __restrict__ i_type) {
    __shared__ int h[N_TYPES];
    if (threadIdx.x < N_TYPES) h[threadIdx.x] = 0;
    __syncthreads();
    int n = blockIdx.x * blockDim.x + threadIdx.x;
    if (n < N_TOK) atomicAdd(&h[load_type(i_type, n)], 1);
    __syncthreads();
    if (threadIdx.x < N_TYPES && h[threadIdx.x]) atomicAdd(&g_counts[threadIdx.x], h[threadIdx.x]);
}

__global__ void tcl_prefix_kernel() {   // 1 warp
    int t = threadIdx.x;
    int c = (t < N_TYPES) ? g_counts[t] : 0;
    int x = c;
    #pragma unroll
    for (int s = 1; s < 32; s <<= 1) {
        int y = __shfl_up_sync(0xffffffffu, x, s);
        if (t >= s) x += y;
    }
    int excl = x - c;
    if (t < N_TYPES) g_offsets[t] = excl;
    if (t == N_TYPES - 1) g_offsets[N_TYPES] = x;
    int nt = (t < N_TYPES) ? (c + BM - 1) / BM : 0;
    int y2 = nt;
    #pragma unroll
    for (int s = 1; s < 32; s <<= 1) {
        int y = __shfl_up_sync(0xffffffffu, y2, s);
        if (t >= s) y2 += y;
    }
    int tbase = y2 - nt;
    if (t == N_TYPES - 1) g_num_tiles = y2;
    if (t < N_TYPES) {
        for (int i = 0; i < nt; i++) {
            int idx = tbase + i;
            g_tile_type[idx]  = t;
            g_tile_start[idx] = excl + i * BM;
            g_tile_rows[idx]  = (c - i * BM < BM) ? (c - i * BM) : BM;
        }
    }
}

__global__ void tcl_scatter_kernel(const void* __restrict__ i_type) {
    int n = blockIdx.x * blockDim.x + threadIdx.x;
    if (n < N_TOK) {
        int t = load_type(i_type, n);
        int pos = g_offsets[t] + atomicAdd(&g_fill[t], 1);
        if (pos >= 0 && pos < N_TOK) g_perm[pos] = n;
    }
}

// ---------------- phase 1.5: pre-split conversions ----------------
__device__ __forceinline__ uint32_t pack2(__nv_bfloat16 a, __nv_bfloat16 b) {
    __nv_bfloat162 t; t.x = a; t.y = b;
    return *reinterpret_cast<uint32_t*>(&t);
}
__device__ __forceinline__ void split2(float x, float y, uint32_t& hi, uint32_t& lo) {
    __nv_bfloat16 hx = __float2bfloat16_rn(x);
    __nv_bfloat16 hy = __float2bfloat16_rn(y);
    float lx = x - __bfloat162float(hx);
    float ly = y - __bfloat162float(hy);
    hi = pack2(hx, hy);
    lo = pack2(__float2bfloat16_rn(lx), __float2bfloat16_rn(ly));
}
__device__ __forceinline__ void split4_store(float4 v, __nv_bfloat16* dh, __nv_bfloat16* dl) {
    uint32_t h0, l0, h1, l1;
    split2(v.x, v.y, h0, l0);
    split2(v.z, v.w, h1, l1);
    *reinterpret_cast<uint2*>(dh) = make_uint2(h0, h1);
    *reinterpret_cast<uint2*>(dl) = make_uint2(l0, l1);
}

__global__ void tcl_convert_w_kernel(const float* __restrict__ weight) {
    size_t i = ((size_t)blockIdx.x * blockDim.x + threadIdx.x) * 4;  // element idx
    float4 v = *reinterpret_cast<const float4*>(weight + i);
    split4_store(v, g_Whi + i, g_Wlo + i);
}

__global__ void tcl_convert_a_kernel(const float* __restrict__ input) {
    // one block = 4 permuted rows; thread t: row blk*4 + t/128, float4 t%128
    int p  = blockIdx.x * 4 + (threadIdx.x >> 7);
    int kq = (threadIdx.x & 127) * 4;
    int tok = g_perm[p];
    float4 v = *reinterpret_cast<const float4*>(input + (size_t)tok * IN_F + kq);
    size_t o = (size_t)p * IN_F + kq;
    split4_store(v, g_Ahi + o, g_Alo + o);
}

// ---------------- mma helpers ----------------
__device__ __forceinline__ uint32_t smem_u32(const void* p) {
    uint32_t a;
    asm("{ .reg .u64 t; cvta.to.shared.u64 t, %1; cvt.u32.u64 %0, t; }" : "=r"(a) : "l"(p));
    return a;
}
__device__ __forceinline__ void ldsm_x4(uint32_t* r, uint32_t addr) {
    asm volatile("ldmatrix.sync.aligned.m8n8.x4.shared.b16 {%0,%1,%2,%3}, [%4];"
                 : "=r"(r[0]), "=r"(r[1]), "=r"(r[2]), "=r"(r[3]) : "r"(addr));
}
__device__ __forceinline__ void mma_bf16(float* c, const uint32_t* a, const uint32_t* b) {
    asm volatile("mma.sync.aligned.m16n8k16.row.col.f32.bf16.bf16.f32 "
                 "{%0,%1,%2,%3}, {%4,%5,%6,%7}, {%8,%9}, {%0,%1,%2,%3};"
                 : "+f"(c[0]), "+f"(c[1]), "+f"(c[2]), "+f"(c[3])
                 : "r"(a[0]), "r"(a[1]), "r"(a[2]), "r"(a[3]), "r"(b[0]), "r"(b[1]));
}
__device__ __forceinline__ void cp16(uint32_t dst, const void* src) {
    asm volatile("cp.async.cg.shared.global [%0], [%1], 16;" :: "r"(dst), "l"(src));
}
#define CP_COMMIT() asm volatile("cp.async.commit_group;" ::: "memory")
template <int N>
__device__ __forceinline__ void cp_wait() {
    asm volatile("cp.async.wait_group %0;" :: "n"(N) : "memory");
}

// ---------------- phase 2: gather-GEMM ----------------
__global__ __launch_bounds__(NTHREADS, 1)
void tcl_gemm_kernel(const float* __restrict__ bias, float* __restrict__ out)
{
    const int mt = blockIdx.y;
    if (mt >= g_num_tiles) return;

    extern __shared__ char smem[];
    const uint32_t sb = smem_u32(smem);
    const int tid  = threadIdx.x;
    const int wid  = tid >> 5;
    const int lane = tid & 31;

    const int nStart   = blockIdx.x * BN;
    const int type     = g_tile_type[mt];
    const int rowStart = g_tile_start[mt];
    const int rows     = g_tile_rows[mt];

    int*   sTok  = (int*)(smem + SM_TOKEN);
    float* sBias = (float*)(smem + SM_BIAS);
    if (tid < BM) sTok[tid] = (tid < rows) ? g_perm[rowStart + tid] : -1;
    if (tid >= 128 && tid < 256) sBias[tid - 128] = bias[type * OUT_F + nStart + tid - 128];

    // producer: 4 x 16B cp.async per thread per slab (one per tile)
    const int prow = tid >> 2;         // 0..127
    const int pseg = tid & 3;          // 16B segment within 64B row
    const size_t aOff = (size_t)(rowStart + prow) * IN_F + pseg * 8;
    const size_t bOff = (size_t)type * OUT_F * IN_F + (size_t)(nStart + prow) * IN_F + pseg * 8;
    const uint32_t dOff = prow * ROW_B + pseg * 16;

    auto issue_slab = [&](int slab) {
        const uint32_t st = sb + SM_STAGE + (slab & (N_STAGES - 1)) * STAGE_B;
        const int k0 = slab * BK;
        cp16(st + A_HI + dOff, g_Ahi + aOff + k0);
        cp16(st + A_LO + dOff, g_Alo + aOff + k0);
        cp16(st + B_HI + dOff, g_Whi + bOff + k0);
        cp16(st + B_LO + dOff, g_Wlo + bOff + k0);
        CP_COMMIT();
    };

    // consumer layout: 4x4 warps of 32(m) x 32(n)  (verbatim from round 4)
    const int wm0 = (wid & 3) * 32;
    const int wn0 = (wid >> 2) * 32;
    const int tile_id = lane >> 3;
    const int tw      = lane & 7;
    const int aoff = (wm0 + tw + (tile_id & 1) * 8) * ROW_B + ((tile_id >> 1) * 8) * 2;
    const int boff = (wn0 + tw + (tile_id >> 1) * 8) * ROW_B + ((tile_id & 1) * 8) * 2;

    float acc[2][4][4];
    #pragma unroll
    for (int mi = 0; mi < 2; mi++)
        #pragma unroll
        for (int nj = 0; nj < 4; nj++)
            #pragma unroll
            for (int e = 0; e < 4; e++) acc[mi][nj][e] = 0.f;

    auto compute = [&](int stg) {
        const uint32_t st = sb + SM_STAGE + stg * STAGE_B;
        #pragma unroll
        for (int kk = 0; kk < BK; kk += 16) {
            uint32_t aH[2][4], aL[2][4], bH[4][2], bL[4][2], r[4];
            #pragma unroll
            for (int mi = 0; mi < 2; mi++) {
                ldsm_x4(aH[mi], st + A_HI + aoff + mi * 16 * ROW_B + kk * 2);
                ldsm_x4(aL[mi], st + A_LO + aoff + mi * 16 * ROW_B + kk * 2);
            }
            #pragma unroll
            for (int g = 0; g < 2; g++) {
                ldsm_x4(r, st + B_HI + boff + g * 16 * ROW_B + kk * 2);
                bH[g * 2][0] = r[0]; bH[g * 2][1] = r[1];
                bH[g * 2 + 1][0] = r[2]; bH[g * 2 + 1][1] = r[3];
                ldsm_x4(r, st + B_LO + boff + g * 16 * ROW_B + kk * 2);
                bL[g * 2][0] = r[0]; bL[g * 2][1] = r[1];
                bL[g * 2 + 1][0] = r[2]; bL[g * 2 + 1][1] = r[3];
            }
            #pragma unroll
            for (int mi = 0; mi < 2; mi++)
                #pragma unroll
                for (int nj = 0; nj < 4; nj++) {
                    mma_bf16(acc[mi][nj], aH[mi], bH[nj]);
                    mma_bf16(acc[mi][nj], aL[mi], bH[nj]);
                    mma_bf16(acc[mi][nj], aH[mi], bL[nj]);
                }
        }
    };

    // ---------------- pipelined mainloop (4 stages, 1 barrier/slab) ----------------
    issue_slab(0);
    issue_slab(1);
    issue_slab(2);
    #pragma unroll 1
    for (int s = 0; s < N_SLABS; s++) {
        if (s + 2 < N_SLABS)      cp_wait<2>();
        else if (s + 1 < N_SLABS) cp_wait<1>();
        else                      cp_wait<0>();
        __syncthreads();
        if (s + 3 < N_SLABS) issue_slab(s + 3);
        compute(s & (N_STAGES - 1));
    }

    // ---------------- epilogue ----------------
    #pragma unroll
    for (int mi = 0; mi < 2; mi++) {
        int r0 = wm0 + mi * 16 + (lane >> 2);
        int r1 = r0 + 8;
        int tok0 = sTok[r0];
        int tok1 = sTok[r1];
        #pragma unroll
        for (int nj = 0; nj < 4; nj++) {
            int col = wn0 + nj * 8 + (lane & 3) * 2;
            float b0 = sBias[col], b1 = sBias[col + 1];
            if (tok0 >= 0) {
                float2 v = make_float2(acc[mi][nj][0] + b0, acc[mi][nj][1] + b1);
                *reinterpret_cast<float2*>(out + (size_t)tok0 * OUT_F + nStart + col) = v;
            }
            if (tok1 >= 0) {
                float2 v = make_float2(acc[mi][nj][2] + b0, acc[mi][nj][3] + b1);
                *reinterpret_cast<float2*>(out + (size_t)tok1 * OUT_F + nStart + col) = v;
            }
        }
    }
}

// ---------------- launcher ----------------
extern "C" void kernel_launch(void* const* d_in, const int* in_sizes, int n_in,
                              void* d_out, int out_size)
{
    const float* input  = (const float*)d_in[0];
    const void*  i_type = d_in[1];
    const float* weight = (const float*)d_in[2];
    const float* bias   = (const float*)d_in[3];
    float*       out    = (float*)d_out;

    cudaFuncSetAttribute(tcl_gemm_kernel,
                         cudaFuncAttributeMaxDynamicSharedMemorySize, SMEM_TOTAL);

    tcl_zero_kernel<<<1, 32>>>();
    tcl_detect_kernel<<<N_TOK / 2 / 256, 256>>>((const int*)i_type);
    tcl_hist_kernel<<<N_TOK / 256, 256>>>(i_type);
    tcl_prefix_kernel<<<1, 32>>>();
    tcl_scatter_kernel<<<N_TOK / 256, 256>>>(i_type);
    tcl_convert_w_kernel<<<(N_TYPES * OUT_F * IN_F) / 4 / 256, 256>>>(weight);
    tcl_convert_a_kernel<<<N_TOK / 4, 512>>>(input);
    tcl_gemm_kernel<<<dim3(OUT_F / BN, MAX_TILES), NTHREADS, SMEM_TOTAL>>>(bias, out);
}

// round 8
// speedup vs baseline: 1.5378x; 1.5378x over previous
#include <cuda_runtime.h>
#include <cuda_fp16.h>
#include <cstdint>

// TypeConditionalLinear on sm_100 (no tcgen05 on non-'a' target).
// out[n] = input[n] @ weight[i_type[n]].T + bias[i_type[n]]
// N=16384, IN=OUT=512, T=16. fp32 in/out.
//
// Round 8 (= round 6 kernel; third submission after two broker-level container
// failures that never reached compile/run):
//   Consumer path is the wall (mma.sync issue-bound), so cut tensor work:
//   fp16 2-product split: out = (aHi + aLo) * fp16(b)   [err ~1.5e-4 << 1e-3]
//   32 MMAs + 12 ldsm per warp-slab (was 48 + 16), B-lo tile eliminated.
//   Launches collapsed 8 -> 4 (detect merged into hist/scatter, counter
//   re-zeroing folded into the GEMM).

#define N_TOK   16384
#define IN_F    512
#define OUT_F   512
#define N_TYPES 16

#define BM 128
#define BN 128
#define BK 32
#define N_SLABS (IN_F / BK)               // 16
#define MAX_TILES (N_TOK / BM + N_TYPES)  // 144
#define NTHREADS 512

#define ROW_B   80                        // smem row stride (32 fp16 = 64B + 16B pad)
#define TILE_B  (128 * ROW_B)             // 10240
#define A_HI    0
#define A_LO    TILE_B
#define B_HI    (2 * TILE_B)
#define STAGE_B (3 * TILE_B)              // 30720
#define SM_TOKEN 0
#define SM_BIAS  512
#define SM_STAGE 1024
#define SMEM_TOTAL (SM_STAGE + 2 * STAGE_B)   // 62464

// ---------------- scratch ----------------
__device__ int g_counts[N_TYPES];         // zero at load; re-zeroed by gemm CTA(0,0)
__device__ int g_fill[N_TYPES];
__device__ int g_offsets[N_TYPES + 1];
__device__ int g_perm[N_TOK];
__device__ int g_tile_type[MAX_TILES];
__device__ int g_tile_start[MAX_TILES];
__device__ int g_tile_rows[MAX_TILES];
__device__ int g_num_tiles;

// ---------------- phase 1: hist (+local dtype detect) ----------------
// i_type is either int64 (odd int32 words all zero) or int32. Each block ORs
// the odd words of its slice; a false int64 verdict needs 256 random values
// in 0..15 to all be zero -> P = 16^-256 = never.
__global__ void tcl_hist_kernel(const int* __restrict__ it32) {
    __shared__ int h[N_TYPES];
    __shared__ int sOdd;
    const int tid = threadIdx.x;
    if (tid < N_TYPES) h[tid] = 0;
    if (tid == 0) sOdd = 0;
    __syncthreads();

    const int i = blockIdx.x * 256 + tid;        // word-pair index, 0..8191
    const int w0 = it32[2 * i];
    const int w1 = it32[2 * i + 1];
    int v = w1;
    #pragma unroll
    for (int s = 16; s > 0; s >>= 1) v |= __shfl_xor_sync(0xffffffffu, v, s);
    if ((tid & 31) == 0 && v) atomicOr(&sOdd, v);
    __syncthreads();

    if (sOdd == 0) {
        // int64: pair i = token i; tokens 8192.. live in words 16384..32767
        atomicAdd(&h[w0 & (N_TYPES - 1)], 1);
        int w2 = it32[2 * (8192 + i)];
        atomicAdd(&h[w2 & (N_TYPES - 1)], 1);
    } else {
        // int32: words 2i, 2i+1 are tokens 2i, 2i+1
        atomicAdd(&h[w0 & (N_TYPES - 1)], 1);
        atomicAdd(&h[w1 & (N_TYPES - 1)], 1);
    }
    __syncthreads();
    if (tid < N_TYPES && h[tid]) atomicAdd(&g_counts[tid], h[tid]);
}

// ---------------- phase 1: prefix + tile table (1 warp) ----------------
__global__ void tcl_prefix_kernel() {
    int t = threadIdx.x;
    int c = (t < N_TYPES) ? g_counts[t] : 0;
    int x = c;
    #pragma unroll
    for (int s = 1; s < 32; s <<= 1) {
        int y = __shfl_up_sync(0xffffffffu, x, s);
        if (t >= s) x += y;
    }
    int excl = x - c;
    if (t < N_TYPES) g_offsets[t] = excl;
    if (t == N_TYPES - 1) g_offsets[N_TYPES] = x;
    int nt = (t < N_TYPES) ? (c + BM - 1) / BM : 0;
    int y2 = nt;
    #pragma unroll
    for (int s = 1; s < 32; s <<= 1) {
        int y = __shfl_up_sync(0xffffffffu, y2, s);
        if (t >= s) y2 += y;
    }
    int tbase = y2 - nt;
    if (t == N_TYPES - 1) g_num_tiles = y2;
    if (t < N_TYPES) {
        for (int i = 0; i < nt; i++) {
            int idx = tbase + i;
            g_tile_type[idx]  = t;
            g_tile_start[idx] = excl + i * BM;
            g_tile_rows[idx]  = (c - i * BM < BM) ? (c - i * BM) : BM;
        }
    }
}

// ---------------- phase 1: scatter (+local detect again) ----------------
__global__ void tcl_scatter_kernel(const int* __restrict__ it32) {
    __shared__ int sOdd;
    const int tid = threadIdx.x;
    if (tid == 0) sOdd = 0;
    __syncthreads();

    const int i = blockIdx.x * 256 + tid;
    const int w0 = it32[2 * i];
    const int w1 = it32[2 * i + 1];
    int v = w1;
    #pragma unroll
    for (int s = 16; s > 0; s >>= 1) v |= __shfl_xor_sync(0xffffffffu, v, s);
    if ((tid & 31) == 0 && v) atomicOr(&sOdd, v);
    __syncthreads();

    if (sOdd == 0) {
        int t0 = w0 & (N_TYPES - 1);
        int p0 = g_offsets[t0] + atomicAdd(&g_fill[t0], 1);
        if (p0 >= 0 && p0 < N_TOK) g_perm[p0] = i;
        int t1 = it32[2 * (8192 + i)] & (N_TYPES - 1);
        int p1 = g_offsets[t1] + atomicAdd(&g_fill[t1], 1);
        if (p1 >= 0 && p1 < N_TOK) g_perm[p1] = 8192 + i;
    } else {
        int t0 = w0 & (N_TYPES - 1);
        int p0 = g_offsets[t0] + atomicAdd(&g_fill[t0], 1);
        if (p0 >= 0 && p0 < N_TOK) g_perm[p0] = 2 * i;
        int t1 = w1 & (N_TYPES - 1);
        int p1 = g_offsets[t1] + atomicAdd(&g_fill[t1], 1);
        if (p1 >= 0 && p1 < N_TOK) g_perm[p1] = 2 * i + 1;
    }
}

// ---------------- mma helpers ----------------
__device__ __forceinline__ uint32_t smem_u32(const void* p) {
    uint32_t a;
    asm("{ .reg .u64 t; cvta.to.shared.u64 t, %1; cvt.u32.u64 %0, t; }" : "=r"(a) : "l"(p));
    return a;
}
__device__ __forceinline__ void ldsm_x4(uint32_t* r, uint32_t addr) {
    asm volatile("ldmatrix.sync.aligned.m8n8.x4.shared.b16 {%0,%1,%2,%3}, [%4];"
                 : "=r"(r[0]), "=r"(r[1]), "=r"(r[2]), "=r"(r[3]) : "r"(addr));
}
__device__ __forceinline__ void mma_f16(float* c, const uint32_t* a, const uint32_t* b) {
    asm volatile("mma.sync.aligned.m16n8k16.row.col.f32.f16.f16.f32 "
                 "{%0,%1,%2,%3}, {%4,%5,%6,%7}, {%8,%9}, {%0,%1,%2,%3};"
                 : "+f"(c[0]), "+f"(c[1]), "+f"(c[2]), "+f"(c[3])
                 : "r"(a[0]), "r"(a[1]), "r"(a[2]), "r"(a[3]), "r"(b[0]), "r"(b[1]));
}

__device__ __forceinline__ uint32_t h2u(__half2 h) { return *reinterpret_cast<uint32_t*>(&h); }

// A split: v -> hi = fp16(v), lo = fp16(v - hi)     (4 floats -> uint2 + uint2)
__device__ __forceinline__ void splitA4(float4 v, uint2& hi, uint2& lo) {
    __half2 h01 = __floats2half2_rn(v.x, v.y);
    __half2 h23 = __floats2half2_rn(v.z, v.w);
    float2 f01 = __half22float2(h01);
    float2 f23 = __half22float2(h23);
    __half2 l01 = __floats2half2_rn(v.x - f01.x, v.y - f01.y);
    __half2 l23 = __floats2half2_rn(v.z - f23.x, v.w - f23.y);
    hi = make_uint2(h2u(h01), h2u(h23));
    lo = make_uint2(h2u(l01), h2u(l23));
}
// B: single fp16 rounding
__device__ __forceinline__ uint2 cvtB4(float4 v) {
    return make_uint2(h2u(__floats2half2_rn(v.x, v.y)), h2u(__floats2half2_rn(v.z, v.w)));
}

// ---------------- phase 2: gather-GEMM ----------------
__global__ __launch_bounds__(NTHREADS, 1)
void tcl_gemm_kernel(const float* __restrict__ input,
                     const float* __restrict__ weight,
                     const float* __restrict__ bias,
                     float* __restrict__ out)
{
    // re-zero bucketing counters for the next kernel_launch call (not read here)
    if (blockIdx.x == 0 && blockIdx.y == 0 && threadIdx.x < N_TYPES) {
        g_counts[threadIdx.x] = 0;
        g_fill[threadIdx.x]   = 0;
    }

    const int mt = blockIdx.y;
    if (mt >= g_num_tiles) return;

    extern __shared__ char smem[];
    const uint32_t sb = smem_u32(smem);
    const int tid  = threadIdx.x;
    const int wid  = tid >> 5;
    const int lane = tid & 31;

    const int nStart   = blockIdx.x * BN;
    const int type     = g_tile_type[mt];
    const int rowStart = g_tile_start[mt];
    const int rows     = g_tile_rows[mt];

    int*   sTok  = (int*)(smem + SM_TOKEN);
    float* sBias = (float*)(smem + SM_BIAS);
    if (tid < BM) sTok[tid] = (tid < rows) ? g_perm[rowStart + tid] : -1;
    if (tid >= 128 && tid < 256) sBias[tid - 128] = bias[type * OUT_F + nStart + tid - 128];
    __syncthreads();

    const float* __restrict__ Wt = weight + (size_t)type * OUT_F * IN_F;

    // producer: thread handles rows pm, pm+64; float4 segment pkq of the 32-float slab row
    const int pm  = tid >> 3;          // 0..63
    const int pkq = tid & 7;           // 0..7

    // warp tile: 4x4 warps of 32(m) x 32(n)
    const int wm0 = (wid & 3) * 32;
    const int wn0 = (wid >> 2) * 32;
    const int tile_id = lane >> 3;
    const int tw      = lane & 7;
    const int aoff = (wm0 + tw + (tile_id & 1) * 8) * ROW_B + ((tile_id >> 1) * 8) * 2;
    const int boff = (wn0 + tw + (tile_id >> 1) * 8) * ROW_B + ((tile_id & 1) * 8) * 2;

    float acc[2][4][4];
    #pragma unroll
    for (int mi = 0; mi < 2; mi++)
        #pragma unroll
        for (int nj = 0; nj < 4; nj++)
            #pragma unroll
            for (int e = 0; e < 4; e++) acc[mi][nj][e] = 0.f;

    float4 va[2], vb[2];

    auto ldg_slab = [&](int slab) {
        const int k0 = slab * BK;
        #pragma unroll
        for (int l = 0; l < 2; l++) {
            int m = pm + l * 64;
            int tok = sTok[m];
            va[l] = make_float4(0.f, 0.f, 0.f, 0.f);
            if (tok >= 0)
                va[l] = *reinterpret_cast<const float4*>(input + (size_t)tok * IN_F + k0 + pkq * 4);
            vb[l] = *reinterpret_cast<const float4*>(Wt + (size_t)(nStart + m) * IN_F + k0 + pkq * 4);
        }
    };

    auto sts_slab = [&](int stg) {
        char* st = smem + SM_STAGE + stg * STAGE_B;
        #pragma unroll
        for (int l = 0; l < 2; l++) {
            int m = pm + l * 64;
            int off = m * ROW_B + pkq * 8;
            uint2 hi, lo;
            splitA4(va[l], hi, lo);
            *reinterpret_cast<uint2*>(st + A_HI + off) = hi;
            *reinterpret_cast<uint2*>(st + A_LO + off) = lo;
            *reinterpret_cast<uint2*>(st + B_HI + off) = cvtB4(vb[l]);
        }
    };

    auto compute = [&](int stg) {
        const uint32_t st = sb + SM_STAGE + stg * STAGE_B;
        #pragma unroll
        for (int kk = 0; kk < BK; kk += 16) {
            uint32_t aH[2][4], aL[2][4], bH[4][2], r[4];
            #pragma unroll
            for (int mi = 0; mi < 2; mi++) {
                ldsm_x4(aH[mi], st + A_HI + aoff + mi * 16 * ROW_B + kk * 2);
                ldsm_x4(aL[mi], st + A_LO + aoff + mi * 16 * ROW_B + kk * 2);
            }
            #pragma unroll
            for (int g = 0; g < 2; g++) {
                ldsm_x4(r, st + B_HI + boff + g * 16 * ROW_B + kk * 2);
                bH[g * 2][0] = r[0]; bH[g * 2][1] = r[1];
                bH[g * 2 + 1][0] = r[2]; bH[g * 2 + 1][1] = r[3];
            }
            #pragma unroll
            for (int mi = 0; mi < 2; mi++)
                #pragma unroll
                for (int nj = 0; nj < 4; nj++) {
                    mma_f16(acc[mi][nj], aH[mi], bH[nj]);
                    mma_f16(acc[mi][nj], aL[mi], bH[nj]);
                }
        }
    };

    // ---------------- pipelined mainloop ----------------
    ldg_slab(0);
    sts_slab(0);
    __syncthreads();
    #pragma unroll 1
    for (int s = 0; s < N_SLABS; s++) {
        if (s + 1 < N_SLABS) ldg_slab(s + 1);
        compute(s & 1);
        if (s + 1 < N_SLABS) sts_slab((s + 1) & 1);
        __syncthreads();
    }

    // ---------------- epilogue ----------------
    #pragma unroll
    for (int mi = 0; mi < 2; mi++) {
        int r0 = wm0 + mi * 16 + (lane >> 2);
        int r1 = r0 + 8;
        int tok0 = sTok[r0];
        int tok1 = sTok[r1];
        #pragma unroll
        for (int nj = 0; nj < 4; nj++) {
            int col = wn0 + nj * 8 + (lane & 3) * 2;
            float b0 = sBias[col], b1 = sBias[col + 1];
            if (tok0 >= 0) {
                float2 v = make_float2(acc[mi][nj][0] + b0, acc[mi][nj][1] + b1);
                *reinterpret_cast<float2*>(out + (size_t)tok0 * OUT_F + nStart + col) = v;
            }
            if (tok1 >= 0) {
                float2 v = make_float2(acc[mi][nj][2] + b0, acc[mi][nj][3] + b1);
                *reinterpret_cast<float2*>(out + (size_t)tok1 * OUT_F + nStart + col) = v;
            }
        }
    }
}

// ---------------- launcher ----------------
extern "C" void kernel_launch(void* const* d_in, const int* in_sizes, int n_in,
                              void* d_out, int out_size)
{
    const float* input  = (const float*)d_in[0];
    const int*   i_type = (const int*)d_in[1];
    const float* weight = (const float*)d_in[2];
    const float* bias   = (const float*)d_in[3];
    float*       out    = (float*)d_out;

    cudaFuncSetAttribute(tcl_gemm_kernel,
                         cudaFuncAttributeMaxDynamicSharedMemorySize, SMEM_TOTAL);

    tcl_hist_kernel<<<32, 256>>>(i_type);
    tcl_prefix_kernel<<<1, 32>>>();
    tcl_scatter_kernel<<<32, 256>>>(i_type);
    tcl_gemm_kernel<<<dim3(OUT_F / BN, MAX_TILES), NTHREADS, SMEM_TOTAL>>>(input, weight, bias, out);
}